// round 1
// baseline (speedup 1.0000x reference)
#include <cuda_runtime.h>
#include <math.h>

// Problem constants
#define BB 4
#define DD 1024
#define NN 4096
#define HH 16
#define KK 128
#define DHH 64

// Scratch (device globals; no allocation in kernel_launch)
__device__ float g_q[(size_t)BB * DD * NN];      // 67MB
__device__ float g_k[(size_t)BB * DD * NN];      // 67MB
__device__ float g_kp[(size_t)BB * DD * KK];     // 2MB
__device__ float g_msg[(size_t)BB * DD * NN];    // 67MB
__device__ float g_msg2[(size_t)BB * DD * NN];   // 67MB
__device__ float g_h[(size_t)BB * 2 * DD * NN];  // 134MB

// ---------------------------------------------------------------------------
// Generic batched "1x1 conv" GEMM:  out[b,m,n] = sum_i W[m,i] * In(b,i,n) + bias[m]
// In(b,i,n) = (i < K1) ? in1[b,i,n] : in2[b,i-K1,n]   (concat along channels)
// Optional fused BatchNorm(eval, eps=1e-3) + ReLU epilogue.
// Tile: 128(M) x 128(N) x 8(K), 256 threads, 8x8 per-thread microtile.
// ---------------------------------------------------------------------------
template <bool CONCAT, bool BNRELU>
__global__ void __launch_bounds__(256) conv_gemm(
    const float* __restrict__ W,
    const float* __restrict__ in1,
    const float* __restrict__ in2,
    const float* __restrict__ bias,
    const float* __restrict__ gamma,
    const float* __restrict__ beta,
    const float* __restrict__ mean,
    const float* __restrict__ var,
    float* __restrict__ outp,
    int M, int Kd, int Nw, int K1)
{
    __shared__ float As[8][128];
    __shared__ float Bs[8][128];

    const int t  = threadIdx.x;
    const int ty = t >> 4;
    const int tx = t & 15;
    const int m0 = blockIdx.y * 128;
    const int n0 = blockIdx.x * 128;
    const int b  = blockIdx.z;

    const float* in1b = in1 + (size_t)b * K1 * Nw;
    const float* in2b = CONCAT ? (in2 + (size_t)b * (size_t)(Kd - K1) * Nw) : nullptr;

    const int ar = t >> 1, ac = (t & 1) * 4;
    const int br = t >> 5, bc = (t & 31) * 4;

    float acc[8][8];
#pragma unroll
    for (int i = 0; i < 8; i++)
#pragma unroll
        for (int j = 0; j < 8; j++) acc[i][j] = 0.f;

    for (int kt = 0; kt < Kd; kt += 8) {
        // A tile: W[m0..m0+127][kt..kt+7], stored transposed
        float4 av = *(const float4*)(W + (size_t)(m0 + ar) * Kd + kt + ac);
        As[ac + 0][ar] = av.x;
        As[ac + 1][ar] = av.y;
        As[ac + 2][ar] = av.z;
        As[ac + 3][ar] = av.w;

        // B tile: In[kt..kt+7][n0..n0+127]  (concat select, warp-uniform branch)
        int ii = kt + br;
        const float* src;
        if (CONCAT && ii >= K1) src = in2b + (size_t)(ii - K1) * Nw;
        else                    src = in1b + (size_t)ii * Nw;
        *(float4*)&Bs[br][bc] = *(const float4*)(src + n0 + bc);

        __syncthreads();

#pragma unroll
        for (int kk = 0; kk < 8; kk++) {
            float a[8], bv[8];
#pragma unroll
            for (int i = 0; i < 8; i++) a[i] = As[kk][ty * 8 + i];
#pragma unroll
            for (int j = 0; j < 8; j++) bv[j] = Bs[kk][tx * 8 + j];
#pragma unroll
            for (int i = 0; i < 8; i++)
#pragma unroll
                for (int j = 0; j < 8; j++)
                    acc[i][j] = fmaf(a[i], bv[j], acc[i][j]);
        }
        __syncthreads();
    }

#pragma unroll
    for (int i = 0; i < 8; i++) {
        const int m = m0 + ty * 8 + i;
        const float bi = bias[m];
        float scale = 1.f, shift = 0.f;
        if (BNRELU) {
            const float inv = rsqrtf(var[m] + 1e-3f);
            scale = gamma[m] * inv;
            shift = beta[m] - mean[m] * scale;
        }
        float* orow = outp + ((size_t)b * M + m) * Nw + n0 + tx * 8;
        float v[8];
#pragma unroll
        for (int j = 0; j < 8; j++) {
            float val = acc[i][j] + bi;
            if (BNRELU) val = fmaxf(fmaf(val, scale, shift), 0.f);
            v[j] = val;
        }
        *(float4*)(orow)     = make_float4(v[0], v[1], v[2], v[3]);
        *(float4*)(orow + 4) = make_float4(v[4], v[5], v[6], v[7]);
    }
}

// ---------------------------------------------------------------------------
// Linformer projection: C[r, c] += A[r, m] * P[m, c]  for r in [0,4096), c in [0,128)
// A = k buffer viewed as [B*D, N] rows; split-K over m (gridDim.y chunks) with
// atomicAdd epilogue (C pre-zeroed via cudaMemsetAsync).
// ---------------------------------------------------------------------------
__global__ void __launch_bounds__(256) proj_gemm(
    const float* __restrict__ A, const float* __restrict__ P, float* __restrict__ C)
{
    __shared__ float As[8][128];
    __shared__ float Bs[8][128];

    const int t  = threadIdx.x;
    const int ty = t >> 4;
    const int tx = t & 15;
    const int r0 = blockIdx.x * 128;
    const int chunk = NN / gridDim.y;
    const int c0 = blockIdx.y * chunk;

    const int ar = t >> 1, ac = (t & 1) * 4;
    const int br = t >> 5, bc = (t & 31) * 4;

    float acc[8][8];
#pragma unroll
    for (int i = 0; i < 8; i++)
#pragma unroll
        for (int j = 0; j < 8; j++) acc[i][j] = 0.f;

    for (int kt = 0; kt < chunk; kt += 8) {
        const int kb = c0 + kt;
        float4 av = *(const float4*)(A + (size_t)(r0 + ar) * NN + kb + ac);
        As[ac + 0][ar] = av.x;
        As[ac + 1][ar] = av.y;
        As[ac + 2][ar] = av.z;
        As[ac + 3][ar] = av.w;
        *(float4*)&Bs[br][bc] = *(const float4*)(P + (size_t)(kb + br) * KK + bc);
        __syncthreads();
#pragma unroll
        for (int kk = 0; kk < 8; kk++) {
            float a[8], bv[8];
#pragma unroll
            for (int i = 0; i < 8; i++) a[i] = As[kk][ty * 8 + i];
#pragma unroll
            for (int j = 0; j < 8; j++) bv[j] = Bs[kk][tx * 8 + j];
#pragma unroll
            for (int i = 0; i < 8; i++)
#pragma unroll
                for (int j = 0; j < 8; j++)
                    acc[i][j] = fmaf(a[i], bv[j], acc[i][j]);
        }
        __syncthreads();
    }

#pragma unroll
    for (int i = 0; i < 8; i++)
#pragma unroll
        for (int j = 0; j < 8; j++)
            atomicAdd(&C[(size_t)(r0 + ty * 8 + i) * KK + tx * 8 + j], acc[i][j]);
}

// ---------------------------------------------------------------------------
// Fused Linformer attention for one (b, h, 128-wide n-tile).
// Channel split: d = dh*H + h  (torch .view(B, DH, H, ...)).
// K/V share the same [DH=64, K=128] slice (share_kv). Scores live in smem,
// one n per thread (per-thread smem column -> conflict-free).
// Dynamic smem: Ks 64*128*4 = 32KB + Es 128*128*4 = 64KB = 96KB.
// ---------------------------------------------------------------------------
__global__ void attn_kernel(const float* __restrict__ q,
                            const float* __restrict__ kp,
                            float* __restrict__ msg)
{
    extern __shared__ float sm[];
    float* Ks = sm;                  // [64][128]
    float* Es = sm + DHH * KK;       // [128 k][128 tid]

    const int tid = threadIdx.x;
    const int n = blockIdx.x * 128 + tid;
    const int h = blockIdx.y;
    const int b = blockIdx.z;

    // Load K/V slice: kp[(b*D + dh*H + h)*K + kk]
#pragma unroll 4
    for (int dh = 0; dh < DHH; dh++)
        Ks[dh * KK + tid] = kp[((size_t)b * DD + (size_t)dh * HH + h) * KK + tid];
    __syncthreads();

    // q vector for this (b, h, n)
    const float* qb = q + ((size_t)b * DD + h) * NN + n;
    float qv[DHH];
#pragma unroll
    for (int dh = 0; dh < DHH; dh++)
        qv[dh] = qb[(size_t)dh * HH * NN];

    // scores (scaled by 1/sqrt(DH)=0.125)
    float mx = -1e30f;
    for (int k = 0; k < KK; k++) {
        float s = 0.f;
#pragma unroll
        for (int dh = 0; dh < DHH; dh++)
            s = fmaf(qv[dh], Ks[dh * KK + k], s);
        s *= 0.125f;
        Es[k * 128 + tid] = s;
        mx = fmaxf(mx, s);
    }

    float sum = 0.f;
    for (int k = 0; k < KK; k++) {
        float e = __expf(Es[k * 128 + tid] - mx);
        Es[k * 128 + tid] = e;
        sum += e;
    }
    const float inv = 1.f / sum;

    // msg[b, dh*H+h, n] = (1/sum) * sum_k e_k * V[dh][k]
    float* msgb = msg + ((size_t)b * DD + h) * NN + n;
#pragma unroll 2
    for (int dh = 0; dh < DHH; dh++) {
        float acc = 0.f;
        for (int k = 0; k < KK; k++)
            acc = fmaf(Es[k * 128 + tid], Ks[dh * KK + k], acc);
        msgb[(size_t)dh * HH * NN] = acc * inv;
    }
}

// ---------------------------------------------------------------------------
extern "C" void kernel_launch(void* const* d_in, const int* in_sizes, int n_in,
                              void* d_out, int out_size)
{
    const float* x       = (const float*)d_in[0];
    const float* source  = (const float*)d_in[1];
    const float* to_q_w  = (const float*)d_in[2];
    const float* to_q_b  = (const float*)d_in[3];
    const float* to_k_w  = (const float*)d_in[4];
    const float* to_k_b  = (const float*)d_in[5];
    const float* proj_k  = (const float*)d_in[6];
    const float* merge_w = (const float*)d_in[7];
    const float* merge_b = (const float*)d_in[8];
    const float* mlp_w1  = (const float*)d_in[9];
    const float* mlp_b1  = (const float*)d_in[10];
    const float* bn_g    = (const float*)d_in[11];
    const float* bn_b    = (const float*)d_in[12];
    const float* bn_m    = (const float*)d_in[13];
    const float* bn_v    = (const float*)d_in[14];
    const float* mlp_w2  = (const float*)d_in[15];
    const float* mlp_b2  = (const float*)d_in[16];
    float* out = (float*)d_out;

    float *q, *k, *kp, *msg, *msg2, *hbuf;
    cudaGetSymbolAddress((void**)&q,    g_q);
    cudaGetSymbolAddress((void**)&k,    g_k);
    cudaGetSymbolAddress((void**)&kp,   g_kp);
    cudaGetSymbolAddress((void**)&msg,  g_msg);
    cudaGetSymbolAddress((void**)&msg2, g_msg2);
    cudaGetSymbolAddress((void**)&hbuf, g_h);

    const dim3 blk(256);

    // 1) q = W_q @ x + b_q
    conv_gemm<false, false><<<dim3(NN / 128, DD / 128, BB), blk>>>(
        to_q_w, x, nullptr, to_q_b, nullptr, nullptr, nullptr, nullptr,
        q, DD, DD, NN, DD);

    // 2) k = W_k @ source + b_k
    conv_gemm<false, false><<<dim3(NN / 128, DD / 128, BB), blk>>>(
        to_k_w, source, nullptr, to_k_b, nullptr, nullptr, nullptr, nullptr,
        k, DD, DD, NN, DD);

    // 3) kp = k @ proj_k   (split-K x8, atomic accumulate)
    cudaMemsetAsync(kp, 0, sizeof(float) * (size_t)BB * DD * KK);
    proj_gemm<<<dim3((BB * DD) / 128, 8), blk>>>(k, proj_k, kp);

    // 4) fused attention -> msg
    cudaFuncSetAttribute(attn_kernel, cudaFuncAttributeMaxDynamicSharedMemorySize,
                         (DHH * KK + 128 * KK) * (int)sizeof(float));
    attn_kernel<<<dim3(NN / 128, HH, BB), dim3(128),
                  (DHH * KK + 128 * KK) * sizeof(float)>>>(q, kp, msg);

    // 5) msg2 = W_merge @ msg + b_merge
    conv_gemm<false, false><<<dim3(NN / 128, DD / 128, BB), blk>>>(
        merge_w, msg, nullptr, merge_b, nullptr, nullptr, nullptr, nullptr,
        msg2, DD, DD, NN, DD);

    // 6) h = relu(BN(W1 @ concat(x, msg2) + b1))
    conv_gemm<true, true><<<dim3(NN / 128, (2 * DD) / 128, BB), blk>>>(
        mlp_w1, x, msg2, mlp_b1, bn_g, bn_b, bn_m, bn_v,
        hbuf, 2 * DD, 2 * DD, NN, DD);

    // 7) out = W2 @ h + b2
    conv_gemm<false, false><<<dim3(NN / 128, DD / 128, BB), blk>>>(
        mlp_w2, hbuf, nullptr, mlp_b2, nullptr, nullptr, nullptr, nullptr,
        out, DD, 2 * DD, NN, 2 * DD);
}